// round 15
// baseline (speedup 1.0000x reference)
#include <cuda_runtime.h>
#include <cuda_fp16.h>
#include <math.h>
#include <stdint.h>

#define Bb 2
#define Nn 2048
#define Dd 768
#define Ee 8
#define Hh 3072
#define Tt (Bb*Nn)        // 4096
#define KKEEP 819         // int(2048*0.4)
#define V_MAX 3.0f
#define FEAT_CLAMP 10.0f

// ---------------- scratch (device globals; no allocation allowed) ----------
__device__ int   g_cnt[Ee];
__device__ int   g_gtok[Tt];
__device__ float g_ggate[Tt];
__device__ float g_gate[Tt];
__device__ float g_score[Tt];
__device__ int   g_list[Ee * Tt];
__device__ __align__(256) __half g_xg[Tt * Dd];
__device__ __align__(256) __half g_y1[(size_t)Tt * Hh];
__device__ __align__(256) float  g_ffn[Tt * Dd];
__device__ __align__(256) float  g_fp[2][(size_t)Tt * Dd];   // split-K partials
__device__ __align__(256) __half g_wt1[(size_t)Ee * Dd * Hh];  // [e][n][k]
__device__ __align__(256) __half g_wt2[(size_t)Ee * Hh * Dd];  // [e][n][k]
__device__ float g_v[Tt];
__device__ float g_thr[Bb];
__device__ float g_fr[Tt], g_fi[Tt];
__device__ float g_br[Tt], g_bi[Tt];

// ---------------- PTX helpers ----------------------------------------------
__device__ __forceinline__ void cp_async16(uint32_t dst, const void* src, int szbytes) {
    asm volatile("cp.async.cg.shared.global [%0], [%1], 16, %2;\n"
                 :: "r"(dst), "l"(src), "r"(szbytes));
}
__device__ __forceinline__ void cp_commit() { asm volatile("cp.async.commit_group;"); }
template<int N> __device__ __forceinline__ void cp_wait() {
    asm volatile("cp.async.wait_group %0;" :: "n"(N));
}
__device__ __forceinline__ uint32_t smem_u32(const void* p) {
    return (uint32_t)__cvta_generic_to_shared(p);
}
__device__ __forceinline__ void ldsm_x4(uint32_t* r, uint32_t addr) {
    asm volatile("ldmatrix.sync.aligned.m8n8.x4.shared.b16 {%0,%1,%2,%3}, [%4];"
        : "=r"(r[0]), "=r"(r[1]), "=r"(r[2]), "=r"(r[3]) : "r"(addr));
}
__device__ __forceinline__ void mma_f16(float* d, const uint32_t* a, const uint32_t* b) {
    asm volatile(
        "mma.sync.aligned.m16n8k16.row.col.f32.f16.f16.f32 "
        "{%0,%1,%2,%3}, {%4,%5,%6,%7}, {%8,%9}, {%0,%1,%2,%3};\n"
        : "+f"(d[0]), "+f"(d[1]), "+f"(d[2]), "+f"(d[3])
        : "r"(a[0]), "r"(a[1]), "r"(a[2]), "r"(a[3]), "r"(b[0]), "r"(b[1]));
}
__device__ __forceinline__ float gelu_tanh(float u) {
    return 0.5f * u * (1.f + tanhf(0.7978845608028654f * (u + 0.044715f * u * u * u)));
}

// transpose tile body: W[k][n] fp32 -> Wt[n][k] fp16 (64k x 32n per block)
__device__ __forceinline__ void tr_tile(const float* __restrict__ Wp,
                                        __half* __restrict__ Wq,
                                        int KD, int ND, int k0, int n0,
                                        float (*tile)[33], int tid) {
    int tx = tid & 31, ty = tid >> 5;
    #pragma unroll
    for (int i = 0; i < 8; i++) {
        int kl = i * 8 + ty;
        tile[kl][tx] = Wp[(size_t)(k0 + kl) * ND + n0 + tx];
    }
    __syncthreads();
    #pragma unroll
    for (int i = 0; i < 4; i++) {
        int nl = i * 8 + ty;
        __half2 h = __floats2half2_rn(tile[2 * tx][nl], tile[2 * tx + 1][nl]);
        *(__half2*)(Wq + (size_t)(n0 + nl) * KD + k0 + 2 * tx) = h;
    }
}

// ---------------- gate + tr1 + tr2 fused launch ------------------------------
__global__ void k_gate_tr(const float* __restrict__ x, const float* __restrict__ Wg,
                          const float* __restrict__ bg, const float* __restrict__ Wm,
                          const float* __restrict__ bm, const float* __restrict__ W1,
                          const float* __restrict__ W2) {
    __shared__ __align__(16) float sbuf[64 * 33];
    int tid = threadIdx.x;
    if (blockIdx.x < Tt) {
        int t = blockIdx.x;
        float* xs = sbuf;
        float* wsum = sbuf + Dd;
        float* logits = sbuf + Dd + 8;
        for (int d = tid; d < Dd; d += 256) xs[d] = x[t * Dd + d];
        __syncthreads();

        int w = tid >> 5, lane = tid & 31;
        float s = 0.f;
        for (int d = lane; d < Dd; d += 32) s += xs[d] * Wg[d * Ee + w];
        #pragma unroll
        for (int o = 16; o; o >>= 1) s += __shfl_xor_sync(0xffffffffu, s, o);
        if (lane == 0) logits[w] = s + bg[w];

        float sm = 0.f;
        for (int d = tid; d < Dd; d += 256) sm += xs[d] * Wm[d];
        #pragma unroll
        for (int o = 16; o; o >>= 1) sm += __shfl_xor_sync(0xffffffffu, sm, o);
        if (lane == 0) wsum[w] = sm;
        __syncthreads();

        if (tid == 0) {
            float tot = 0.f;
            #pragma unroll
            for (int q = 0; q < 8; q++) tot += wsum[q];
            g_score[t] = 1.f / (1.f + expf(-(tot + bm[0])));
            float mx = logits[0]; int am = 0;
            #pragma unroll
            for (int e = 1; e < Ee; e++) if (logits[e] > mx) { mx = logits[e]; am = e; }
            float ssum = 0.f;
            #pragma unroll
            for (int e = 0; e < Ee; e++) ssum += expf(logits[e] - mx);
            g_gate[t] = 1.f / ssum;
            int pos = atomicAdd(&g_cnt[am], 1);
            g_list[am * Tt + pos] = t;
        }
    } else if (blockIdx.x < Tt + 9216) {
        int q = blockIdx.x - Tt;
        int e = q / ((Hh / 32) * (Dd / 64));
        int rem = q % ((Hh / 32) * (Dd / 64));
        int ky = rem / (Hh / 32);
        int nx = rem % (Hh / 32);
        tr_tile(W1 + (size_t)e * Dd * Hh, (__half*)g_wt1 + (size_t)e * Dd * Hh,
                Dd, Hh, ky * 64, nx * 32, (float(*)[33])sbuf, tid);
    } else {
        int q = blockIdx.x - Tt - 9216;
        int e = q / ((Dd / 32) * (Hh / 64));
        int rem = q % ((Dd / 32) * (Hh / 64));
        int ky = rem / (Dd / 32);
        int nx = rem % (Dd / 32);
        tr_tile(W2 + (size_t)e * Hh * Dd, (__half*)g_wt2 + (size_t)e * Hh * Dd,
                Hh, Dd, ky * 64, nx * 32, (float(*)[33])sbuf, tid);
    }
}

// helper: expert + offset from gathered row index, via local prefix of g_cnt
__device__ __forceinline__ void row_to_expert(int g, int& e, int& off) {
    int acc = 0, ee = 0, oo = 0;
    #pragma unroll
    for (int q = 0; q < Ee; q++) {
        int c = g_cnt[q];
        if (g >= acc) { ee = q; oo = acc; }
        acc += c;
    }
    e = ee; off = oo;
}

// gather x rows into expert-grouped buffer, converted to fp16
__global__ void k_gather(const float* __restrict__ x) {
    int g = blockIdx.x;
    __shared__ int s_tok;
    if (threadIdx.x == 0) {
        int e, off;
        row_to_expert(g, e, off);
        int token = g_list[e * Tt + (g - off)];
        g_gtok[g] = token; g_ggate[g] = g_gate[token];
        s_tok = token;
    }
    __syncthreads();
    int token = s_tok;
    int i = threadIdx.x;
    float4 v = ((const float4*)(x + (size_t)token * Dd))[i];
    __half2* dst = (__half2*)(g_xg + (size_t)g * Dd);
    dst[i * 2]     = __floats2half2_rn(v.x, v.y);
    dst[i * 2 + 1] = __floats2half2_rn(v.z, v.w);
}

// ---------------- fp16 tensor-core grouped GEMM ----------------------------
// 64x128 tile, 128 threads (4 warps of 32x64), K-chunk 32, 3-stage cp.async,
// ldmatrix.x4, 4 CTAs/SM, ONE barrier per chunk, prefetch distance 2:
//   cp_wait<1> -> barrier -> issue load(c+2) -> compute(c)
// Load latency gets two full compute phases to land.
#define GST 3
#define CHK 32
#define ROWH 40
#define A_H (64 * ROWH)
#define STAGEH ((64 + 128) * ROWH)        // 7680 halfs = 15360 B
#define GSMEM (GST * STAGEH * 2)          // 46080 bytes

template<int KD, int ND, bool DOGELU, int NSPL>
__global__ __launch_bounds__(128, 4) void k_gemm(const float* __restrict__ ball) {
    extern __shared__ __align__(16) __half sh[];
    int tid = threadIdx.x;

    const __half* Aall = DOGELU ? (const __half*)g_xg : (const __half*)g_y1;
    const __half* Wt   = DOGELU ? (const __half*)g_wt1 : (const __half*)g_wt2;

    int e = blockIdx.x >> 6;
    int m0 = (blockIdx.x & 63) * 64;
    int cnt = g_cnt[e];
    if (m0 >= cnt) return;
    int goff = 0;
    #pragma unroll
    for (int q = 0; q < Ee; q++) goff += (q < e) ? g_cnt[q] : 0;
    const __half* Ap = Aall + (size_t)goff * KD;
    const __half* Bt = Wt + (size_t)e * KD * ND;
    const float* bias = ball + (size_t)e * ND;
    int n0 = blockIdx.y * 128;
    int z = (NSPL > 1) ? blockIdx.z : 0;
    int kbase = z * (KD / NSPL);

    int lane = tid & 31, warp = tid >> 5;
    int wm = warp & 1, wn = warp >> 1;     // warp tile rows wm*32, cols wn*64
    int gid = lane >> 2, tg = lane & 3;

    float acc[2][8][4];
    #pragma unroll
    for (int mi = 0; mi < 2; mi++)
        #pragma unroll
        for (int ni = 0; ni < 8; ni++)
            #pragma unroll
            for (int q = 0; q < 4; q++) acc[mi][ni][q] = 0.f;

    const int NCH = KD / NSPL / CHK;

    auto load_chunk = [&](int c, int s) {
        int k0 = kbase + c * CHK;
        __half* a = sh + s * STAGEH;
        __half* b = sh + s * STAGEH + A_H;
        #pragma unroll
        for (int i = tid; i < 256; i += 128) {       // A: 64 rows x 64B
            int m = i >> 2, seg = i & 3;
            int ok = (m0 + m < cnt);
            int mrow = ok ? (m0 + m) : 0;
            cp_async16(smem_u32(a + m * ROWH + seg * 8),
                       Ap + (size_t)mrow * KD + k0 + seg * 8, ok ? 16 : 0);
        }
        #pragma unroll
        for (int i = tid; i < 512; i += 128) {       // B: 128 n-rows x 64B
            int n = i >> 2, seg = i & 3;
            cp_async16(smem_u32(b + n * ROWH + seg * 8),
                       Bt + (size_t)(n0 + n) * KD + k0 + seg * 8, 16);
        }
        cp_commit();
    };

    load_chunk(0, 0);
    load_chunk(1, 1);
    int arow = wm * 32 + (lane & 15);
    int acol = (lane >> 4) * 8;
    int brow = wn * 64 + (lane & 7) + (lane >> 4) * 8;
    int bcol = ((lane >> 3) & 1) * 8;

    for (int c = 0; c < NCH; c++) {
        if (c + 1 < NCH) { cp_wait<1>(); } else { cp_wait<0>(); }
        __syncthreads();   // publish chunk c; stage (c+2)%3 certified free
        if (c + 2 < NCH) load_chunk(c + 2, (c + 2) % GST);

        const __half* a = sh + (c % GST) * STAGEH;
        const __half* b = sh + (c % GST) * STAGEH + A_H;

        #pragma unroll
        for (int k16 = 0; k16 < CHK / 16; k16++) {
            int kc = k16 * 16;
            uint32_t af[2][4];
            #pragma unroll
            for (int mi = 0; mi < 2; mi++)
                ldsm_x4(af[mi], smem_u32(a + (arow + mi * 16) * ROWH + kc + acol));
            uint32_t bf[8][2];
            #pragma unroll
            for (int p = 0; p < 4; p++) {
                uint32_t r[4];
                ldsm_x4(r, smem_u32(b + (brow + p * 16) * ROWH + kc + bcol));
                bf[2 * p][0] = r[0]; bf[2 * p][1] = r[1];
                bf[2 * p + 1][0] = r[2]; bf[2 * p + 1][1] = r[3];
            }
            #pragma unroll
            for (int mi = 0; mi < 2; mi++)
                #pragma unroll
                for (int ni = 0; ni < 8; ni++)
                    mma_f16(acc[mi][ni], af[mi], bf[ni]);
        }
    }

    // epilogue: c0=(gid,2tg) c1=(gid,2tg+1) c2=(gid+8,2tg) c3=(gid+8,2tg+1)
    if (DOGELU) {
        #pragma unroll
        for (int mi = 0; mi < 2; mi++) {
            int rloc0 = m0 + wm * 32 + mi * 16 + gid;
            #pragma unroll
            for (int half = 0; half < 2; half++) {
                int rloc = rloc0 + half * 8;
                if (rloc >= cnt) continue;
                int grow = goff + rloc;
                __half* orow = (__half*)g_y1 + (size_t)grow * ND + n0;
                #pragma unroll
                for (int ni = 0; ni < 8; ni++) {
                    int c = wn * 64 + ni * 8 + tg * 2;
                    float v0 = acc[mi][ni][half * 2 + 0] + bias[n0 + c];
                    float v1 = acc[mi][ni][half * 2 + 1] + bias[n0 + c + 1];
                    *(__half2*)(orow + c) =
                        __floats2half2_rn(gelu_tanh(v0), gelu_tanh(v1));
                }
            }
        }
    } else {
        float* fp = g_fp[z];
        float bsc = (z == 0) ? 1.f : 0.f;
        #pragma unroll
        for (int mi = 0; mi < 2; mi++) {
            int rloc0 = m0 + wm * 32 + mi * 16 + gid;
            #pragma unroll
            for (int half = 0; half < 2; half++) {
                int rloc = rloc0 + half * 8;
                if (rloc >= cnt) continue;
                int grow = goff + rloc;
                int token = g_gtok[grow];
                float gate = g_ggate[grow];
                float* orow = fp + (size_t)token * ND + n0;
                #pragma unroll
                for (int ni = 0; ni < 8; ni++) {
                    int c = wn * 64 + ni * 8 + tg * 2;
                    orow[c]     = gate * (acc[mi][ni][half * 2 + 0] + bsc * bias[n0 + c]);
                    orow[c + 1] = gate * (acc[mi][ni][half * 2 + 1] + bsc * bias[n0 + c + 1]);
                }
            }
        }
    }
}

// combine split-K partials -> g_ffn; fused v = clip(ffn . Wv + bv)
__global__ void k_comb(const float* __restrict__ Wv, const float* __restrict__ bv) {
    int t = blockIdx.x;
    int tid = threadIdx.x;           // 192 threads, one float4 each
    int lane = tid & 31, warp = tid >> 5;
    __shared__ float red[6];
    const float4* p0 = (const float4*)(g_fp[0] + (size_t)t * Dd);
    const float4* p1 = (const float4*)(g_fp[1] + (size_t)t * Dd);
    float4 a = p0[tid], b = p1[tid];
    float4 w = ((const float4*)Wv)[tid];
    float4 o;
    o.x = a.x + b.x; o.y = a.y + b.y; o.z = a.z + b.z; o.w = a.w + b.w;
    ((float4*)(g_ffn + (size_t)t * Dd))[tid] = o;
    float s = o.x * w.x + o.y * w.y + o.z * w.z + o.w * w.w;
    #pragma unroll
    for (int off = 16; off; off >>= 1) s += __shfl_xor_sync(0xffffffffu, s, off);
    if (lane == 0) red[warp] = s;
    __syncthreads();
    if (tid == 0) {
        float tot = red[0] + red[1] + red[2] + red[3] + red[4] + red[5] + bv[0];
        g_v[t] = fminf(fmaxf(tot, -V_MAX), V_MAX);
    }
}

// ---------------- combined threshold (bitonic) + BK scan -------------------
struct CM2 { float r00,i00,r01,i01,r10,i10,r11,i11; };
__device__ __forceinline__ CM2 cm2_mul(const CM2& A, const CM2& B) {
    CM2 C;
    C.r00 = A.r00*B.r00 - A.i00*B.i00 + A.r01*B.r10 - A.i01*B.i10;
    C.i00 = A.r00*B.i00 + A.i00*B.r00 + A.r01*B.i10 + A.i01*B.r10;
    C.r01 = A.r00*B.r01 - A.i00*B.i01 + A.r01*B.r11 - A.i01*B.i11;
    C.i01 = A.r00*B.i01 + A.i00*B.r01 + A.r01*B.i11 + A.i01*B.r11;
    C.r10 = A.r10*B.r00 - A.i10*B.i00 + A.r11*B.r10 - A.i11*B.i10;
    C.i10 = A.r10*B.i00 + A.i10*B.r00 + A.r11*B.i10 + A.i11*B.r10;
    C.r11 = A.r10*B.r01 - A.i10*B.i01 + A.r11*B.r11 - A.i11*B.i11;
    C.i11 = A.r10*B.i01 + A.i10*B.r01 + A.r11*B.i11 + A.i11*B.r11;
    return C;
}
__device__ __forceinline__ void cm2_norm(CM2& A) {
    float mx = fmaxf(fmaxf(fabsf(A.r00)+fabsf(A.i00), fabsf(A.r01)+fabsf(A.i01)),
                     fmaxf(fabsf(A.r10)+fabsf(A.i10), fabsf(A.r11)+fabsf(A.i11)));
    float sc = 1.f / fmaxf(mx, 1e-30f);
    A.r00*=sc; A.i00*=sc; A.r01*=sc; A.i01*=sc;
    A.r10*=sc; A.i10*=sc; A.r11*=sc; A.i11*=sc;
}
__device__ __forceinline__ CM2 cm2_shfl_up(const CM2& A, int off) {
    CM2 B;
    B.r00 = __shfl_up_sync(0xffffffffu, A.r00, off);
    B.i00 = __shfl_up_sync(0xffffffffu, A.i00, off);
    B.r01 = __shfl_up_sync(0xffffffffu, A.r01, off);
    B.i01 = __shfl_up_sync(0xffffffffu, A.i01, off);
    B.r10 = __shfl_up_sync(0xffffffffu, A.r10, off);
    B.i10 = __shfl_up_sync(0xffffffffu, A.i10, off);
    B.r11 = __shfl_up_sync(0xffffffffu, A.r11, off);
    B.i11 = __shfl_up_sync(0xffffffffu, A.i11, off);
    return B;
}

__global__ void k_thrbk() {
    if (blockIdx.x < Bb) {
        __shared__ float s[Nn];
        int b = blockIdx.x, tid = threadIdx.x;
        for (int i = tid; i < Nn; i += 1024) s[i] = g_score[b * Nn + i];
        for (int k = 2; k <= Nn; k <<= 1) {
            for (int j = k >> 1; j > 0; j >>= 1) {
                __syncthreads();
                for (int i = tid; i < Nn; i += 1024) {
                    int ixj = i ^ j;
                    if (ixj > i) {
                        bool up = ((i & k) == 0);
                        float a = s[i], c = s[ixj];
                        if ((a > c) == up) { s[i] = c; s[ixj] = a; }
                    }
                }
            }
        }
        __syncthreads();
        if (tid == 0) g_thr[b] = s[Nn - KKEEP];
    } else if (threadIdx.x < 32) {
        int id = blockIdx.x - Bb;
        int b = id >> 1, dir = id & 1;
        int lane = threadIdx.x;
        const int CH = Nn / 32;
        const float* vv = g_v + b * Nn;

        CM2 P = {1,0, 0,0, 0,0, 1,0};
        for (int j = 0; j < CH; j++) {
            int idx = lane * CH + j;
            int pos = dir ? (Nn - 1 - idx) : idx;
            float dr = vv[pos];
            CM2 M = {dr, -1.f, -1.f, 0.f, 1.f, 0.f, 0.f, 0.f};
            P = cm2_mul(M, P);
            cm2_norm(P);
        }
        CM2 S = P;
        #pragma unroll
        for (int off = 1; off < 32; off <<= 1) {
            CM2 O = cm2_shfl_up(S, off);
            if (lane >= off) { S = cm2_mul(S, O); cm2_norm(S); }
        }
        CM2 E = cm2_shfl_up(S, 1);
        float ar, ai;
        if (lane == 0) { ar = 1e18f; ai = 0.f; }
        else {
            float nr = E.r00 * 1e18f + E.r01, ni = E.i00 * 1e18f + E.i01;
            float qr = E.r10 * 1e18f + E.r11, qi = E.i10 * 1e18f + E.i11;
            float den = qr * qr + qi * qi;
            if (den < 1e-36f) { ar = 1e18f; ai = 0.f; }
            else { ar = (nr * qr + ni * qi) / den; ai = (ni * qr - nr * qi) / den; }
        }
        float* outr = dir ? g_br : g_fr;
        float* outi = dir ? g_bi : g_fi;
        for (int j = 0; j < CH; j++) {
            int idx = lane * CH + j;
            int pos = dir ? (Nn - 1 - idx) : idx;
            float dr = vv[pos];
            float den = ar * ar + ai * ai;
            float inv = 1.f / den;
            float nr = dr - ar * inv;
            float ni = -1.f + ai * inv;
            ar = nr; ai = ni;
            outr[b * Nn + pos] = ar; outi[b * Nn + pos] = ai;
        }
    }
    // reset g_cnt for next graph replay
    if (blockIdx.x == 0 && threadIdx.x < Ee) {
        __syncthreads();
        g_cnt[threadIdx.x] = 0;
    }
}

// flat elementwise epilogue: out = ffn + bk*(feats @ Wo + bo), float4 lanes
__global__ void k_out(const float* __restrict__ Wo, const float* __restrict__ bo,
                      const float* __restrict__ bk, float* __restrict__ out) {
    int e4 = blockIdx.x * 256 + threadIdx.x;
    int t = e4 / (Dd / 4);
    int d = (e4 % (Dd / 4)) * 4;
    int b = t >> 11;
    float v  = g_v[t];
    float cr = g_fr[t] + g_br[t] - v;
    float ci = g_fi[t] + g_bi[t] + 1.f;
    float den = cr * cr + ci * ci;
    float m = (g_score[t] >= g_thr[b]) ? 1.f : 0.f;
    float fr = fminf(fmaxf(( cr / den) * m, -FEAT_CLAMP), FEAT_CLAMP);
    float fi = fminf(fmaxf((-ci / den) * m, -FEAT_CLAMP), FEAT_CLAMP);
    float s = bk[0];
    float4 f  = *(const float4*)(g_ffn + (size_t)t * Dd + d);
    float4 w1 = *(const float4*)(Wo + d);
    float4 w2 = *(const float4*)(Wo + Dd + d);
    float4 bb = *(const float4*)(bo + d);
    float4 o;
    o.x = f.x + s * (fr * w1.x + fi * w2.x + bb.x);
    o.y = f.y + s * (fr * w1.y + fi * w2.y + bb.y);
    o.z = f.z + s * (fr * w1.z + fi * w2.z + bb.z);
    o.w = f.w + s * (fr * w1.w + fi * w2.w + bb.w);
    *(float4*)(out + (size_t)t * Dd + d) = o;
}

// ---------------- launch ---------------------------------------------------
extern "C" void kernel_launch(void* const* d_in, const int* in_sizes, int n_in,
                              void* d_out, int out_size) {
    const float* x   = (const float*)d_in[0];
    const float* Wg  = (const float*)d_in[1];
    const float* bg  = (const float*)d_in[2];
    const float* W1  = (const float*)d_in[3];
    const float* b1  = (const float*)d_in[4];
    const float* W2  = (const float*)d_in[5];
    const float* b2  = (const float*)d_in[6];
    const float* Wv  = (const float*)d_in[7];
    const float* bv  = (const float*)d_in[8];
    const float* Wm  = (const float*)d_in[9];
    const float* bm  = (const float*)d_in[10];
    const float* Wo  = (const float*)d_in[11];
    const float* bo  = (const float*)d_in[12];
    const float* bks = (const float*)d_in[13];
    float* out = (float*)d_out;

    static int attr_done = 0;
    if (!attr_done) {
        cudaFuncSetAttribute(k_gemm<Dd, Hh, true , 1>,
                             cudaFuncAttributeMaxDynamicSharedMemorySize, GSMEM);
        cudaFuncSetAttribute(k_gemm<Hh, Dd, false, 2>,
                             cudaFuncAttributeMaxDynamicSharedMemorySize, GSMEM);
        attr_done = 1;
    }

    k_gate_tr<<<Tt + 2 * 9216, 256>>>(x, Wg, bg, Wm, bm, W1, W2);
    k_gather<<<Tt, 192>>>(x);
    k_gemm<Dd, Hh, true , 1><<<dim3(Ee * 64, Hh / 128),    128, GSMEM>>>(b1);
    k_gemm<Hh, Dd, false, 2><<<dim3(Ee * 64, Dd / 128, 2), 128, GSMEM>>>(b2);
    k_comb<<<Tt, 192>>>(Wv, bv);
    k_thrbk<<<3 * Bb, 1024>>>();
    k_out<<<(Tt * Dd / 4) / 256, 256>>>(Wo, bo, bks, out);
}

// round 16
// speedup vs baseline: 1.1299x; 1.1299x over previous
#include <cuda_runtime.h>
#include <cuda_fp16.h>
#include <math.h>
#include <stdint.h>

#define Bb 2
#define Nn 2048
#define Dd 768
#define Ee 8
#define Hh 3072
#define Tt (Bb*Nn)        // 4096
#define KKEEP 819         // int(2048*0.4)
#define V_MAX 3.0f
#define FEAT_CLAMP 10.0f
#define NSPL2 3           // GEMM2 split-K factor

// ---------------- scratch (device globals; no allocation allowed) ----------
__device__ int   g_cnt[Ee];
__device__ int   g_gtok[Tt];
__device__ float g_ggate[Tt];
__device__ float g_gate[Tt];
__device__ float g_score[Tt];
__device__ int   g_list[Ee * Tt];
__device__ __align__(256) __half g_xg[Tt * Dd];
__device__ __align__(256) __half g_y1[(size_t)Tt * Hh];
__device__ __align__(256) float  g_ffn[Tt * Dd];
__device__ __align__(256) float  g_fp[NSPL2][(size_t)Tt * Dd];   // split-K partials
__device__ __align__(256) __half g_wt1[(size_t)Ee * Dd * Hh];  // [e][n][k]
__device__ __align__(256) __half g_wt2[(size_t)Ee * Hh * Dd];  // [e][n][k]
__device__ float g_v[Tt];
__device__ float g_thr[Bb];
__device__ float g_fr[Tt], g_fi[Tt];
__device__ float g_br[Tt], g_bi[Tt];

// ---------------- PTX helpers ----------------------------------------------
__device__ __forceinline__ void cp_async16(uint32_t dst, const void* src, int szbytes) {
    asm volatile("cp.async.cg.shared.global [%0], [%1], 16, %2;\n"
                 :: "r"(dst), "l"(src), "r"(szbytes));
}
__device__ __forceinline__ void cp_commit() { asm volatile("cp.async.commit_group;"); }
template<int N> __device__ __forceinline__ void cp_wait() {
    asm volatile("cp.async.wait_group %0;" :: "n"(N));
}
__device__ __forceinline__ uint32_t smem_u32(const void* p) {
    return (uint32_t)__cvta_generic_to_shared(p);
}
__device__ __forceinline__ void ldsm_x4(uint32_t* r, uint32_t addr) {
    asm volatile("ldmatrix.sync.aligned.m8n8.x4.shared.b16 {%0,%1,%2,%3}, [%4];"
        : "=r"(r[0]), "=r"(r[1]), "=r"(r[2]), "=r"(r[3]) : "r"(addr));
}
__device__ __forceinline__ void mma_f16(float* d, const uint32_t* a, const uint32_t* b) {
    asm volatile(
        "mma.sync.aligned.m16n8k16.row.col.f32.f16.f16.f32 "
        "{%0,%1,%2,%3}, {%4,%5,%6,%7}, {%8,%9}, {%0,%1,%2,%3};\n"
        : "+f"(d[0]), "+f"(d[1]), "+f"(d[2]), "+f"(d[3])
        : "r"(a[0]), "r"(a[1]), "r"(a[2]), "r"(a[3]), "r"(b[0]), "r"(b[1]));
}
__device__ __forceinline__ float gelu_tanh(float u) {
    return 0.5f * u * (1.f + tanhf(0.7978845608028654f * (u + 0.044715f * u * u * u)));
}

// transpose tile body: W[k][n] fp32 -> Wt[n][k] fp16 (64k x 32n per block)
__device__ __forceinline__ void tr_tile(const float* __restrict__ Wp,
                                        __half* __restrict__ Wq,
                                        int KD, int ND, int k0, int n0,
                                        float (*tile)[33], int tid) {
    int tx = tid & 31, ty = tid >> 5;
    #pragma unroll
    for (int i = 0; i < 8; i++) {
        int kl = i * 8 + ty;
        tile[kl][tx] = Wp[(size_t)(k0 + kl) * ND + n0 + tx];
    }
    __syncthreads();
    #pragma unroll
    for (int i = 0; i < 4; i++) {
        int nl = i * 8 + ty;
        __half2 h = __floats2half2_rn(tile[2 * tx][nl], tile[2 * tx + 1][nl]);
        *(__half2*)(Wq + (size_t)(n0 + nl) * KD + k0 + 2 * tx) = h;
    }
}

// ---------------- gate + tr1 + tr2 fused launch ------------------------------
__global__ void k_gate_tr(const float* __restrict__ x, const float* __restrict__ Wg,
                          const float* __restrict__ bg, const float* __restrict__ Wm,
                          const float* __restrict__ bm, const float* __restrict__ W1,
                          const float* __restrict__ W2) {
    __shared__ __align__(16) float sbuf[64 * 33];
    int tid = threadIdx.x;
    if (blockIdx.x < Tt) {
        int t = blockIdx.x;
        float* xs = sbuf;
        float* wsum = sbuf + Dd;
        float* logits = sbuf + Dd + 8;
        for (int d = tid; d < Dd; d += 256) xs[d] = x[t * Dd + d];
        __syncthreads();

        int w = tid >> 5, lane = tid & 31;
        float s = 0.f;
        for (int d = lane; d < Dd; d += 32) s += xs[d] * Wg[d * Ee + w];
        #pragma unroll
        for (int o = 16; o; o >>= 1) s += __shfl_xor_sync(0xffffffffu, s, o);
        if (lane == 0) logits[w] = s + bg[w];

        float sm = 0.f;
        for (int d = tid; d < Dd; d += 256) sm += xs[d] * Wm[d];
        #pragma unroll
        for (int o = 16; o; o >>= 1) sm += __shfl_xor_sync(0xffffffffu, sm, o);
        if (lane == 0) wsum[w] = sm;
        __syncthreads();

        if (tid == 0) {
            float tot = 0.f;
            #pragma unroll
            for (int q = 0; q < 8; q++) tot += wsum[q];
            g_score[t] = 1.f / (1.f + expf(-(tot + bm[0])));
            float mx = logits[0]; int am = 0;
            #pragma unroll
            for (int e = 1; e < Ee; e++) if (logits[e] > mx) { mx = logits[e]; am = e; }
            float ssum = 0.f;
            #pragma unroll
            for (int e = 0; e < Ee; e++) ssum += expf(logits[e] - mx);
            g_gate[t] = 1.f / ssum;
            int pos = atomicAdd(&g_cnt[am], 1);
            g_list[am * Tt + pos] = t;
        }
    } else if (blockIdx.x < Tt + 9216) {
        int q = blockIdx.x - Tt;
        int e = q / ((Hh / 32) * (Dd / 64));
        int rem = q % ((Hh / 32) * (Dd / 64));
        int ky = rem / (Hh / 32);
        int nx = rem % (Hh / 32);
        tr_tile(W1 + (size_t)e * Dd * Hh, (__half*)g_wt1 + (size_t)e * Dd * Hh,
                Dd, Hh, ky * 64, nx * 32, (float(*)[33])sbuf, tid);
    } else {
        int q = blockIdx.x - Tt - 9216;
        int e = q / ((Dd / 32) * (Hh / 64));
        int rem = q % ((Dd / 32) * (Hh / 64));
        int ky = rem / (Dd / 32);
        int nx = rem % (Dd / 32);
        tr_tile(W2 + (size_t)e * Hh * Dd, (__half*)g_wt2 + (size_t)e * Hh * Dd,
                Hh, Dd, ky * 64, nx * 32, (float(*)[33])sbuf, tid);
    }
}

// helper: expert + offset from gathered row index, via local prefix of g_cnt
__device__ __forceinline__ void row_to_expert(int g, int& e, int& off) {
    int acc = 0, ee = 0, oo = 0;
    #pragma unroll
    for (int q = 0; q < Ee; q++) {
        int c = g_cnt[q];
        if (g >= acc) { ee = q; oo = acc; }
        acc += c;
    }
    e = ee; off = oo;
}

// gather x rows into expert-grouped buffer, converted to fp16
__global__ void k_gather(const float* __restrict__ x) {
    int g = blockIdx.x;
    __shared__ int s_tok;
    if (threadIdx.x == 0) {
        int e, off;
        row_to_expert(g, e, off);
        int token = g_list[e * Tt + (g - off)];
        g_gtok[g] = token; g_ggate[g] = g_gate[token];
        s_tok = token;
    }
    __syncthreads();
    int token = s_tok;
    int i = threadIdx.x;
    float4 v = ((const float4*)(x + (size_t)token * Dd))[i];
    __half2* dst = (__half2*)(g_xg + (size_t)g * Dd);
    dst[i * 2]     = __floats2half2_rn(v.x, v.y);
    dst[i * 2 + 1] = __floats2half2_rn(v.z, v.w);
}

// ---------------- fp16 tensor-core grouped GEMM ----------------------------
// 64x128 tile, 128 threads (4 warps of 32x64), K-chunk 64, 2-stage cp.async,
// ldmatrix.x4, 4 CTAs/SM, ONE barrier per chunk (round-14 structure).
// NSPL: split-K factor (GEMM2 uses 3; parts write disjoint fp32 partials).
#define GST 2
#define CHK 64
#define ROWH 72
#define A_H (64 * ROWH)
#define STAGEH ((64 + 128) * ROWH)
#define GSMEM (GST * STAGEH * 2)         // 55296 bytes

template<int KD, int ND, bool DOGELU, int NSPL>
__global__ __launch_bounds__(128, 4) void k_gemm(const float* __restrict__ ball) {
    extern __shared__ __align__(16) __half sh[];
    int tid = threadIdx.x;

    const __half* Aall = DOGELU ? (const __half*)g_xg : (const __half*)g_y1;
    const __half* Wt   = DOGELU ? (const __half*)g_wt1 : (const __half*)g_wt2;

    int e = blockIdx.x >> 6;
    int m0 = (blockIdx.x & 63) * 64;
    int cnt = g_cnt[e];
    if (m0 >= cnt) return;
    int goff = 0;
    #pragma unroll
    for (int q = 0; q < Ee; q++) goff += (q < e) ? g_cnt[q] : 0;
    const __half* Ap = Aall + (size_t)goff * KD;
    const __half* Bt = Wt + (size_t)e * KD * ND;
    const float* bias = ball + (size_t)e * ND;
    int n0 = blockIdx.y * 128;
    int z = (NSPL > 1) ? blockIdx.z : 0;
    int kbase = z * (KD / NSPL);

    int lane = tid & 31, warp = tid >> 5;
    int wm = warp & 1, wn = warp >> 1;     // warp tile rows wm*32, cols wn*64
    int gid = lane >> 2, tg = lane & 3;

    float acc[2][8][4];
    #pragma unroll
    for (int mi = 0; mi < 2; mi++)
        #pragma unroll
        for (int ni = 0; ni < 8; ni++)
            #pragma unroll
            for (int q = 0; q < 4; q++) acc[mi][ni][q] = 0.f;

    const int NCH = KD / NSPL / CHK;

    auto load_chunk = [&](int c, int s) {
        int k0 = kbase + c * CHK;
        __half* a = sh + s * STAGEH;
        __half* b = sh + s * STAGEH + A_H;
        #pragma unroll
        for (int i = tid; i < 512; i += 128) {       // A: 64 rows x 128B
            int m = i >> 3, seg = i & 7;
            int ok = (m0 + m < cnt);
            int mrow = ok ? (m0 + m) : 0;
            cp_async16(smem_u32(a + m * ROWH + seg * 8),
                       Ap + (size_t)mrow * KD + k0 + seg * 8, ok ? 16 : 0);
        }
        #pragma unroll
        for (int i = tid; i < 1024; i += 128) {      // B: 128 n-rows x 128B
            int n = i >> 3, seg = i & 7;
            cp_async16(smem_u32(b + n * ROWH + seg * 8),
                       Bt + (size_t)(n0 + n) * KD + k0 + seg * 8, 16);
        }
        cp_commit();
    };

    load_chunk(0, 0);
    int arow = wm * 32 + (lane & 15);
    int acol = (lane >> 4) * 8;
    int brow = wn * 64 + (lane & 7) + (lane >> 4) * 8;
    int bcol = ((lane >> 3) & 1) * 8;

    for (int c = 0; c < NCH; c++) {
        cp_wait<0>();
        __syncthreads();   // publish chunk c; buffer (c+1)&1 certified free
        if (c + 1 < NCH) load_chunk(c + 1, (c + 1) & 1);

        const __half* a = sh + (c & 1) * STAGEH;
        const __half* b = sh + (c & 1) * STAGEH + A_H;

        #pragma unroll
        for (int k16 = 0; k16 < CHK / 16; k16++) {
            int kc = k16 * 16;
            uint32_t af[2][4];
            #pragma unroll
            for (int mi = 0; mi < 2; mi++)
                ldsm_x4(af[mi], smem_u32(a + (arow + mi * 16) * ROWH + kc + acol));
            uint32_t bf[8][2];
            #pragma unroll
            for (int p = 0; p < 4; p++) {
                uint32_t r[4];
                ldsm_x4(r, smem_u32(b + (brow + p * 16) * ROWH + kc + bcol));
                bf[2 * p][0] = r[0]; bf[2 * p][1] = r[1];
                bf[2 * p + 1][0] = r[2]; bf[2 * p + 1][1] = r[3];
            }
            #pragma unroll
            for (int mi = 0; mi < 2; mi++)
                #pragma unroll
                for (int ni = 0; ni < 8; ni++)
                    mma_f16(acc[mi][ni], af[mi], bf[ni]);
        }
    }

    // epilogue: c0=(gid,2tg) c1=(gid,2tg+1) c2=(gid+8,2tg) c3=(gid+8,2tg+1)
    if (DOGELU) {
        #pragma unroll
        for (int mi = 0; mi < 2; mi++) {
            int rloc0 = m0 + wm * 32 + mi * 16 + gid;
            #pragma unroll
            for (int half = 0; half < 2; half++) {
                int rloc = rloc0 + half * 8;
                if (rloc >= cnt) continue;
                int grow = goff + rloc;
                __half* orow = (__half*)g_y1 + (size_t)grow * ND + n0;
                #pragma unroll
                for (int ni = 0; ni < 8; ni++) {
                    int c = wn * 64 + ni * 8 + tg * 2;
                    float v0 = acc[mi][ni][half * 2 + 0] + bias[n0 + c];
                    float v1 = acc[mi][ni][half * 2 + 1] + bias[n0 + c + 1];
                    *(__half2*)(orow + c) =
                        __floats2half2_rn(gelu_tanh(v0), gelu_tanh(v1));
                }
            }
        }
    } else {
        float* fp = g_fp[z];
        float bsc = (z == 0) ? 1.f : 0.f;
        #pragma unroll
        for (int mi = 0; mi < 2; mi++) {
            int rloc0 = m0 + wm * 32 + mi * 16 + gid;
            #pragma unroll
            for (int half = 0; half < 2; half++) {
                int rloc = rloc0 + half * 8;
                if (rloc >= cnt) continue;
                int grow = goff + rloc;
                int token = g_gtok[grow];
                float gate = g_ggate[grow];
                float* orow = fp + (size_t)token * ND + n0;
                #pragma unroll
                for (int ni = 0; ni < 8; ni++) {
                    int c = wn * 64 + ni * 8 + tg * 2;
                    orow[c]     = gate * (acc[mi][ni][half * 2 + 0] + bsc * bias[n0 + c]);
                    orow[c + 1] = gate * (acc[mi][ni][half * 2 + 1] + bsc * bias[n0 + c + 1]);
                }
            }
        }
    }
}

// combine split-K partials -> g_ffn; fused v = clip(ffn . Wv + bv)
__global__ void k_comb(const float* __restrict__ Wv, const float* __restrict__ bv) {
    int t = blockIdx.x;
    int tid = threadIdx.x;           // 192 threads, one float4 each
    int lane = tid & 31, warp = tid >> 5;
    __shared__ float red[6];
    float4 o = ((const float4*)(g_fp[0] + (size_t)t * Dd))[tid];
    #pragma unroll
    for (int zz = 1; zz < NSPL2; zz++) {
        float4 p = ((const float4*)(g_fp[zz] + (size_t)t * Dd))[tid];
        o.x += p.x; o.y += p.y; o.z += p.z; o.w += p.w;
    }
    float4 w = ((const float4*)Wv)[tid];
    ((float4*)(g_ffn + (size_t)t * Dd))[tid] = o;
    float s = o.x * w.x + o.y * w.y + o.z * w.z + o.w * w.w;
    #pragma unroll
    for (int off = 16; off; off >>= 1) s += __shfl_xor_sync(0xffffffffu, s, off);
    if (lane == 0) red[warp] = s;
    __syncthreads();
    if (tid == 0) {
        float tot = red[0] + red[1] + red[2] + red[3] + red[4] + red[5] + bv[0];
        g_v[t] = fminf(fmaxf(tot, -V_MAX), V_MAX);
    }
}

// ---------------- combined threshold (bitonic) + BK scan -------------------
struct CM2 { float r00,i00,r01,i01,r10,i10,r11,i11; };
__device__ __forceinline__ CM2 cm2_mul(const CM2& A, const CM2& B) {
    CM2 C;
    C.r00 = A.r00*B.r00 - A.i00*B.i00 + A.r01*B.r10 - A.i01*B.i10;
    C.i00 = A.r00*B.i00 + A.i00*B.r00 + A.r01*B.i10 + A.i01*B.r10;
    C.r01 = A.r00*B.r01 - A.i00*B.i01 + A.r01*B.r11 - A.i01*B.i11;
    C.i01 = A.r00*B.i01 + A.i00*B.r01 + A.r01*B.i11 + A.i01*B.r11;
    C.r10 = A.r10*B.r00 - A.i10*B.i00 + A.r11*B.r10 - A.i11*B.i10;
    C.i10 = A.r10*B.i00 + A.i10*B.r00 + A.r11*B.i10 + A.i11*B.r10;
    C.r11 = A.r10*B.r01 - A.i10*B.i01 + A.r11*B.r11 - A.i11*B.i11;
    C.i11 = A.r10*B.i01 + A.i10*B.r01 + A.r11*B.i11 + A.i11*B.r11;
    return C;
}
__device__ __forceinline__ void cm2_norm(CM2& A) {
    float mx = fmaxf(fmaxf(fabsf(A.r00)+fabsf(A.i00), fabsf(A.r01)+fabsf(A.i01)),
                     fmaxf(fabsf(A.r10)+fabsf(A.i10), fabsf(A.r11)+fabsf(A.i11)));
    float sc = 1.f / fmaxf(mx, 1e-30f);
    A.r00*=sc; A.i00*=sc; A.r01*=sc; A.i01*=sc;
    A.r10*=sc; A.i10*=sc; A.r11*=sc; A.i11*=sc;
}
__device__ __forceinline__ CM2 cm2_shfl_up(const CM2& A, int off) {
    CM2 B;
    B.r00 = __shfl_up_sync(0xffffffffu, A.r00, off);
    B.i00 = __shfl_up_sync(0xffffffffu, A.i00, off);
    B.r01 = __shfl_up_sync(0xffffffffu, A.r01, off);
    B.i01 = __shfl_up_sync(0xffffffffu, A.i01, off);
    B.r10 = __shfl_up_sync(0xffffffffu, A.r10, off);
    B.i10 = __shfl_up_sync(0xffffffffu, A.i10, off);
    B.r11 = __shfl_up_sync(0xffffffffu, A.r11, off);
    B.i11 = __shfl_up_sync(0xffffffffu, A.i11, off);
    return B;
}

__global__ void k_thrbk() {
    if (blockIdx.x < Bb) {
        __shared__ float s[Nn];
        int b = blockIdx.x, tid = threadIdx.x;
        for (int i = tid; i < Nn; i += 1024) s[i] = g_score[b * Nn + i];
        for (int k = 2; k <= Nn; k <<= 1) {
            for (int j = k >> 1; j > 0; j >>= 1) {
                __syncthreads();
                for (int i = tid; i < Nn; i += 1024) {
                    int ixj = i ^ j;
                    if (ixj > i) {
                        bool up = ((i & k) == 0);
                        float a = s[i], c = s[ixj];
                        if ((a > c) == up) { s[i] = c; s[ixj] = a; }
                    }
                }
            }
        }
        __syncthreads();
        if (tid == 0) g_thr[b] = s[Nn - KKEEP];
    } else if (threadIdx.x < 32) {
        int id = blockIdx.x - Bb;
        int b = id >> 1, dir = id & 1;
        int lane = threadIdx.x;
        const int CH = Nn / 32;
        const float* vv = g_v + b * Nn;

        CM2 P = {1,0, 0,0, 0,0, 1,0};
        for (int j = 0; j < CH; j++) {
            int idx = lane * CH + j;
            int pos = dir ? (Nn - 1 - idx) : idx;
            float dr = vv[pos];
            CM2 M = {dr, -1.f, -1.f, 0.f, 1.f, 0.f, 0.f, 0.f};
            P = cm2_mul(M, P);
            cm2_norm(P);
        }
        CM2 S = P;
        #pragma unroll
        for (int off = 1; off < 32; off <<= 1) {
            CM2 O = cm2_shfl_up(S, off);
            if (lane >= off) { S = cm2_mul(S, O); cm2_norm(S); }
        }
        CM2 E = cm2_shfl_up(S, 1);
        float ar, ai;
        if (lane == 0) { ar = 1e18f; ai = 0.f; }
        else {
            float nr = E.r00 * 1e18f + E.r01, ni = E.i00 * 1e18f + E.i01;
            float qr = E.r10 * 1e18f + E.r11, qi = E.i10 * 1e18f + E.i11;
            float den = qr * qr + qi * qi;
            if (den < 1e-36f) { ar = 1e18f; ai = 0.f; }
            else { ar = (nr * qr + ni * qi) / den; ai = (ni * qr - nr * qi) / den; }
        }
        float* outr = dir ? g_br : g_fr;
        float* outi = dir ? g_bi : g_fi;
        for (int j = 0; j < CH; j++) {
            int idx = lane * CH + j;
            int pos = dir ? (Nn - 1 - idx) : idx;
            float dr = vv[pos];
            float den = ar * ar + ai * ai;
            float inv = 1.f / den;
            float nr = dr - ar * inv;
            float ni = -1.f + ai * inv;
            ar = nr; ai = ni;
            outr[b * Nn + pos] = ar; outi[b * Nn + pos] = ai;
        }
    }
    // reset g_cnt for next graph replay
    if (blockIdx.x == 0 && threadIdx.x < Ee) {
        __syncthreads();
        g_cnt[threadIdx.x] = 0;
    }
}

// flat elementwise epilogue: out = ffn + bk*(feats @ Wo + bo), float4 lanes
__global__ void k_out(const float* __restrict__ Wo, const float* __restrict__ bo,
                      const float* __restrict__ bk, float* __restrict__ out) {
    int e4 = blockIdx.x * 256 + threadIdx.x;
    int t = e4 / (Dd / 4);
    int d = (e4 % (Dd / 4)) * 4;
    int b = t >> 11;
    float v  = g_v[t];
    float cr = g_fr[t] + g_br[t] - v;
    float ci = g_fi[t] + g_bi[t] + 1.f;
    float den = cr * cr + ci * ci;
    float m = (g_score[t] >= g_thr[b]) ? 1.f : 0.f;
    float fr = fminf(fmaxf(( cr / den) * m, -FEAT_CLAMP), FEAT_CLAMP);
    float fi = fminf(fmaxf((-ci / den) * m, -FEAT_CLAMP), FEAT_CLAMP);
    float s = bk[0];
    float4 f  = *(const float4*)(g_ffn + (size_t)t * Dd + d);
    float4 w1 = *(const float4*)(Wo + d);
    float4 w2 = *(const float4*)(Wo + Dd + d);
    float4 bb = *(const float4*)(bo + d);
    float4 o;
    o.x = f.x + s * (fr * w1.x + fi * w2.x + bb.x);
    o.y = f.y + s * (fr * w1.y + fi * w2.y + bb.y);
    o.z = f.z + s * (fr * w1.z + fi * w2.z + bb.z);
    o.w = f.w + s * (fr * w1.w + fi * w2.w + bb.w);
    *(float4*)(out + (size_t)t * Dd + d) = o;
}

// ---------------- launch ---------------------------------------------------
extern "C" void kernel_launch(void* const* d_in, const int* in_sizes, int n_in,
                              void* d_out, int out_size) {
    const float* x   = (const float*)d_in[0];
    const float* Wg  = (const float*)d_in[1];
    const float* bg  = (const float*)d_in[2];
    const float* W1  = (const float*)d_in[3];
    const float* b1  = (const float*)d_in[4];
    const float* W2  = (const float*)d_in[5];
    const float* b2  = (const float*)d_in[6];
    const float* Wv  = (const float*)d_in[7];
    const float* bv  = (const float*)d_in[8];
    const float* Wm  = (const float*)d_in[9];
    const float* bm  = (const float*)d_in[10];
    const float* Wo  = (const float*)d_in[11];
    const float* bo  = (const float*)d_in[12];
    const float* bks = (const float*)d_in[13];
    float* out = (float*)d_out;

    static int attr_done = 0;
    if (!attr_done) {
        cudaFuncSetAttribute(k_gemm<Dd, Hh, true , 1>,
                             cudaFuncAttributeMaxDynamicSharedMemorySize, GSMEM);
        cudaFuncSetAttribute(k_gemm<Hh, Dd, false, NSPL2>,
                             cudaFuncAttributeMaxDynamicSharedMemorySize, GSMEM);
        attr_done = 1;
    }

    k_gate_tr<<<Tt + 2 * 9216, 256>>>(x, Wg, bg, Wm, bm, W1, W2);
    k_gather<<<Tt, 192>>>(x);
    k_gemm<Dd, Hh, true , 1    ><<<dim3(Ee * 64, Hh / 128),        128, GSMEM>>>(b1);
    k_gemm<Hh, Dd, false, NSPL2><<<dim3(Ee * 64, Dd / 128, NSPL2), 128, GSMEM>>>(b2);
    k_comb<<<Tt, 192>>>(Wv, bv);
    k_thrbk<<<3 * Bb, 1024>>>();
    k_out<<<(Tt * Dd / 4) / 256, 256>>>(Wo, bo, bks, out);
}